// round 4
// baseline (speedup 1.0000x reference)
#include <cuda_runtime.h>
#include <math.h>

#define HH 1024
#define WW 1024
#define BBATCH 8
#define PLANE (HH*WW)          // 1<<20
#define NPIX (BBATCH*PLANE)    // 8<<20

__device__ float g_E[NPIX];    // edge_soft
__device__ float g_A[NPIX];    // ping
__device__ float g_B2[NPIX];   // pong
__device__ float g_acc[3];     // mask_sum, chroma_sum, hue_sum

__device__ __forceinline__ float4 ld4(const float* p){ return *reinterpret_cast<const float4*>(p); }
__device__ __forceinline__ void st4(float* p, float4 v){ *reinterpret_cast<float4*>(p) = v; }

template<bool M>
__device__ __forceinline__ float rop(float a, float b){ return M ? fmaxf(a,b) : fminf(a,b); }

// ---------------------------------------------------------------------------
// Pass 1: Sobel edge (zero-padded), |gx|+|gy|, max over channels, clip(/0.5,0,1)
// ---------------------------------------------------------------------------
#define ET 8

__device__ __forceinline__ void load_row6(const float* p, int x0, float* r)
{
    r[0] = (x0 > 0) ? p[x0-1] : 0.f;
    float4 v = ld4(p + x0); r[1]=v.x; r[2]=v.y; r[3]=v.z; r[4]=v.w;
    r[5] = (x0+4 < WW) ? p[x0+4] : 0.f;
}

__device__ __forceinline__ void zero_row6(float* r)
{
    #pragma unroll
    for (int i=0;i<6;i++) r[i]=0.f;
}

__global__ void __launch_bounds__(256) edge_kernel(const float* __restrict__ t)
{
    int x0  = threadIdx.x << 2;
    int grp = blockIdx.x;
    int b   = grp / (HH/ET);
    int y0  = (grp % (HH/ET)) * ET;

    float g[ET][4];
    #pragma unroll
    for (int k=0;k<ET;k++){ g[k][0]=0.f; g[k][1]=0.f; g[k][2]=0.f; g[k][3]=0.f; }

    #pragma unroll
    for (int c = 0; c < 3; c++) {
        const float* p = t + (size_t)b*3*PLANE + (size_t)c*PLANE;
        float row[3][6];
        if (y0 > 0) load_row6(p + (size_t)(y0-1)*WW, x0, row[0]);
        else        zero_row6(row[0]);
        load_row6(p + (size_t)y0*WW, x0, row[1]);

        #pragma unroll
        for (int k = 0; k < ET; k++) {
            int ynext = y0 + k + 1;
            float* nr = row[(k+2)%3];
            if (ynext <= HH-1) load_row6(p + (size_t)ynext*WW, x0, nr);
            else               zero_row6(nr);

            const float* a  = row[ k   %3];
            const float* bm = row[(k+1)%3];
            const float* cm = row[(k+2)%3];

            float s[6], d[6];
            #pragma unroll
            for (int i=0;i<6;i++){ s[i] = fmaf(2.f, bm[i], a[i]+cm[i]); d[i] = cm[i]-a[i]; }
            #pragma unroll
            for (int j=0;j<4;j++){
                float gx = s[j+2] - s[j];
                float gy = fmaf(2.f, d[j+1], d[j]+d[j+2]);
                g[k][j] = fmaxf(g[k][j], fabsf(gx) + fabsf(gy));
            }
        }
    }

    float* obase = g_E + (size_t)b*PLANE + x0;
    #pragma unroll
    for (int k=0;k<ET;k++){
        float4 o;
        o.x = fminf(g[k][0]*2.f, 1.f);
        o.y = fminf(g[k][1]*2.f, 1.f);
        o.z = fminf(g[k][2]*2.f, 1.f);
        o.w = fminf(g[k][3]*2.f, 1.f);
        st4(obase + (size_t)(y0+k)*WW, o);
    }
}

// ---------------------------------------------------------------------------
// Horizontal 11-tap pool of one row -> float4 (shared-prefix reduction)
// ---------------------------------------------------------------------------
template<bool M>
__device__ __forceinline__ float4 hrow11(const float* __restrict__ p, int x0)
{
    float a[14];   // positions x0-5 .. x0+8
    if (x0 >= 8 && x0 <= WW-12) {
        float4 v0 = ld4(p+x0-8), v1 = ld4(p+x0-4), v2 = ld4(p+x0), v3 = ld4(p+x0+4), v4 = ld4(p+x0+8);
        a[0]=v0.w;
        a[1]=v1.x; a[2]=v1.y; a[3]=v1.z; a[4]=v1.w;
        a[5]=v2.x; a[6]=v2.y; a[7]=v2.z; a[8]=v2.w;
        a[9]=v3.x; a[10]=v3.y; a[11]=v3.z; a[12]=v3.w;
        a[13]=v4.x;
    } else {
        #pragma unroll
        for (int i=0;i<14;i++){
            int xx = x0-5+i; xx = xx < 0 ? 0 : (xx > WW-1 ? WW-1 : xx);
            a[i] = p[xx];
        }
    }
    float C = a[3];
    #pragma unroll
    for (int i=4;i<=10;i++) C = rop<M>(C, a[i]);
    float t12 = rop<M>(a[1],  a[2]);
    float t23 = rop<M>(a[11], a[12]);
    float4 o;
    o.x = rop<M>(C, rop<M>(a[0], t12));
    o.y = rop<M>(C, rop<M>(t12,  a[11]));
    o.z = rop<M>(rop<M>(C, a[2]),  t23);
    o.w = rop<M>(rop<M>(C, a[13]), t23);
    return o;
}

// ---------------------------------------------------------------------------
// Fused 11x11 separable pool: h-pool each incoming row into an 11-deep
// register ring, reduce vertically. T output rows per block.
// Clamped rows/cols == inf-padded reduce_window for max/min.
// ---------------------------------------------------------------------------
#define PT 8

template<bool M, int T>
__device__ __forceinline__ void pool2d11_body(const float* __restrict__ in, float* __restrict__ out)
{
    int x0  = threadIdx.x << 2;
    int grp = blockIdx.x;
    int b   = grp / (HH/T);
    int y0  = (grp % (HH/T)) * T;
    const float* base  = in  + (size_t)b*PLANE;
    float*       obase = out + (size_t)b*PLANE + x0;

    float4 r[11];
    #pragma unroll
    for (int i = 0; i < 10; i++) {
        int yy = y0 - 5 + i; yy = yy < 0 ? 0 : yy;
        r[i] = hrow11<M>(base + (size_t)yy*WW, x0);
    }
    #pragma unroll
    for (int k = 0; k < T; k++) {
        int yy = y0 + k + 5; yy = yy > HH-1 ? HH-1 : yy;
        r[(10+k) % 11] = hrow11<M>(base + (size_t)yy*WW, x0);
        float4 o = r[0];
        #pragma unroll
        for (int i=1;i<11;i++){
            o.x = rop<M>(o.x, r[i].x); o.y = rop<M>(o.y, r[i].y);
            o.z = rop<M>(o.z, r[i].z); o.w = rop<M>(o.w, r[i].w);
        }
        st4(obase + (size_t)(y0+k)*WW, o);
    }
}

__global__ void __launch_bounds__(256) k_dilate2d(){ pool2d11_body<true , PT>(g_E, g_A); }
__global__ void __launch_bounds__(256) k_erode2d (){ pool2d11_body<false, PT>(g_A, g_B2); }

// ---------------------------------------------------------------------------
// Fused: mask = relu(closed - edge), then 5x5 max (h5 inline + 5-deep v ring)
// ---------------------------------------------------------------------------
__device__ __forceinline__ float4 maskh5_row(const float* __restrict__ pc,
                                             const float* __restrict__ pe, int x0)
{
    float m[8];   // positions x0-2 .. x0+5
    if (x0 >= 4 && x0 <= WW-8) {
        float4 c0 = ld4(pc+x0-4), c1 = ld4(pc+x0), c2 = ld4(pc+x0+4);
        float4 e0 = ld4(pe+x0-4), e1 = ld4(pe+x0), e2 = ld4(pe+x0+4);
        m[0]=fmaxf(c0.z-e0.z,0.f); m[1]=fmaxf(c0.w-e0.w,0.f);
        m[2]=fmaxf(c1.x-e1.x,0.f); m[3]=fmaxf(c1.y-e1.y,0.f);
        m[4]=fmaxf(c1.z-e1.z,0.f); m[5]=fmaxf(c1.w-e1.w,0.f);
        m[6]=fmaxf(c2.x-e2.x,0.f); m[7]=fmaxf(c2.y-e2.y,0.f);
    } else {
        #pragma unroll
        for (int i=0;i<8;i++){
            int xx = x0-2+i; xx = xx < 0 ? 0 : (xx > WW-1 ? WW-1 : xx);
            m[i] = fmaxf(pc[xx]-pe[xx], 0.f);
        }
    }
    float C   = fmaxf(m[3], m[4]);
    float t12 = fmaxf(m[1], m[2]);
    float t56 = fmaxf(m[5], m[6]);
    float4 o;
    o.x = fmaxf(C, fmaxf(m[0], t12));
    o.y = fmaxf(C, fmaxf(t12,  m[5]));
    o.z = fmaxf(fmaxf(C, m[2]), t56);
    o.w = fmaxf(fmaxf(C, m[7]), t56);
    return o;
}

#define MT 8

__global__ void __launch_bounds__(256) k_mask2d()
{
    int x0  = threadIdx.x << 2;
    int grp = blockIdx.x;
    int b   = grp / (HH/MT);
    int y0  = (grp % (HH/MT)) * MT;
    const float* cb = g_B2 + (size_t)b*PLANE;   // closed
    const float* eb = g_E  + (size_t)b*PLANE;   // edge
    float*    obase = g_A  + (size_t)b*PLANE + x0;

    float4 r[5];
    #pragma unroll
    for (int i = 0; i < 4; i++) {
        int yy = y0 - 2 + i; yy = yy < 0 ? 0 : yy;
        r[i] = maskh5_row(cb + (size_t)yy*WW, eb + (size_t)yy*WW, x0);
    }
    #pragma unroll
    for (int k = 0; k < MT; k++) {
        int yy = y0 + k + 2; yy = yy > HH-1 ? HH-1 : yy;
        r[(4+k) % 5] = maskh5_row(cb + (size_t)yy*WW, eb + (size_t)yy*WW, x0);
        float4 o = r[0];
        #pragma unroll
        for (int i=1;i<5;i++){
            o.x = fmaxf(o.x, r[i].x); o.y = fmaxf(o.y, r[i].y);
            o.z = fmaxf(o.z, r[i].z); o.w = fmaxf(o.w, r[i].w);
        }
        st4(obase + (size_t)(y0+k)*WW, o);
    }
}

// ---------------------------------------------------------------------------
// Loss: OKLab a,b for pred & target only where mask > 0 (exact: terms are *mask)
// ---------------------------------------------------------------------------
__device__ __forceinline__ float s2l(float x)
{
    x = fminf(fmaxf(x, 0.f), 1.f);
    return (x <= 0.04045f) ? x * (1.f/12.92f)
                           : powf((x + 0.055f) * (1.f/1.055f), 2.4f);
}

__device__ __forceinline__ void oklab_ab(float r, float g, float bl, float& A, float& Bc)
{
    float lr = s2l(r), lg = s2l(g), lb = s2l(bl);
    float l = 0.4122214708f*lr + 0.5363325363f*lg + 0.0514459929f*lb;
    float m = 0.2119034982f*lr + 0.6806995451f*lg + 0.1073969566f*lb;
    float s = 0.0883024619f*lr + 0.2817188376f*lg + 0.6299787005f*lb;
    l = cbrtf(fmaxf(l, 1e-10f));
    m = cbrtf(fmaxf(m, 1e-10f));
    s = cbrtf(fmaxf(s, 1e-10f));
    A  = 1.9779984951f*l - 2.428592205f*m + 0.4505937099f*s;
    Bc = 0.0259040371f*l + 0.7827717662f*m - 0.808675766f*s;
}

__global__ void __launch_bounds__(256) k_loss(const float* __restrict__ pred,
                                              const float* __restrict__ tgt)
{
    const int NG = NPIX / 4;
    float msum = 0.f, chroma = 0.f, hue = 0.f;

    for (int gidx = blockIdx.x*blockDim.x + threadIdx.x; gidx < NG;
         gidx += gridDim.x*blockDim.x)
    {
        int pix = gidx << 2;
        float4 mk = ld4(g_A + pix);
        msum += (mk.x + mk.y) + (mk.z + mk.w);
        if (mk.x > 0.f || mk.y > 0.f || mk.z > 0.f || mk.w > 0.f) {
            int b   = pix >> 20;
            int rem = pix & (PLANE-1);
            size_t base = (size_t)b*3*PLANE + rem;
            float mv[4] = {mk.x, mk.y, mk.z, mk.w};
            #pragma unroll 1
            for (int j=0;j<4;j++){
                float m = mv[j];
                if (m > 0.f) {
                    float pa,pb,ta,tb;
                    oklab_ab(pred[base+j], pred[base+j+PLANE], pred[base+j+2*PLANE], pa, pb);
                    oklab_ab(tgt [base+j], tgt [base+j+PLANE], tgt [base+j+2*PLANE], ta, tb);
                    float Cp = sqrtf(fmaf(pa,pa, pb*pb) + 1e-12f);
                    float Cg = sqrtf(fmaf(ta,ta, tb*tb) + 1e-12f);
                    chroma += fabsf(Cp - Cg) * m;
                    float cosd = (pa*ta + pb*tb) / (Cp*Cg + 1e-12f);
                    cosd = fminf(fmaxf(cosd, -1.f), 1.f);
                    hue += fmaxf(Cg, 0.01f) * (1.f - cosd) * m;
                }
            }
        }
    }

    #pragma unroll
    for (int o=16; o; o>>=1){
        msum   += __shfl_xor_sync(0xffffffffu, msum,   o);
        chroma += __shfl_xor_sync(0xffffffffu, chroma, o);
        hue    += __shfl_xor_sync(0xffffffffu, hue,    o);
    }
    __shared__ float sm[3][8];
    int w = threadIdx.x >> 5, lane = threadIdx.x & 31;
    if (lane == 0){ sm[0][w]=msum; sm[1][w]=chroma; sm[2][w]=hue; }
    __syncthreads();
    if (threadIdx.x == 0){
        float a=0.f, c=0.f, h=0.f;
        #pragma unroll
        for (int i=0;i<8;i++){ a+=sm[0][i]; c+=sm[1][i]; h+=sm[2][i]; }
        atomicAdd(&g_acc[0], a);
        atomicAdd(&g_acc[1], c);
        atomicAdd(&g_acc[2], h);
    }
}

__global__ void k_zero(){ if (threadIdx.x < 3) g_acc[threadIdx.x] = 0.f; }

__global__ void k_fin(float* out)
{
    float ms = fmaxf(g_acc[0], 1.f);
    out[0] = g_acc[1]/ms + 2.f*(g_acc[2]/ms);
}

// ---------------------------------------------------------------------------
extern "C" void kernel_launch(void* const* d_in, const int* in_sizes, int n_in,
                              void* d_out, int out_size)
{
    const float* pred = (const float*)d_in[0];
    const float* tgt  = (const float*)d_in[1];
    float* out = (float*)d_out;

    const int egrid = BBATCH*HH/ET;   // 1024
    const int pgrid = BBATCH*HH/PT;   // 1024
    const int mgrid = BBATCH*HH/MT;   // 1024
    dim3 blk(256);

    k_zero     <<<1, 32>>>();
    edge_kernel<<<egrid, blk>>>(tgt);     // target -> g_E
    k_dilate2d <<<pgrid, blk>>>();        // g_E  -> g_A   (11x11 max)
    k_erode2d  <<<pgrid, blk>>>();        // g_A  -> g_B2  (11x11 min)
    k_mask2d   <<<mgrid, blk>>>();        // (g_B2, g_E) -> g_A (mask + 5x5 max)
    k_loss     <<<1184,  blk>>>(pred, tgt);
    k_fin      <<<1, 1>>>(out);
}

// round 5
// speedup vs baseline: 1.0469x; 1.0469x over previous
#include <cuda_runtime.h>
#include <math.h>

#define HH 1024
#define WW 1024
#define BBATCH 8
#define PLANE (HH*WW)          // 1<<20
#define NPIX (BBATCH*PLANE)    // 8<<20

__device__ float g_E[NPIX];    // edge_soft
__device__ float g_A[NPIX];    // ping
__device__ float g_B2[NPIX];   // pong
__device__ float g_acc[3];     // mask_sum, chroma_sum, hue_sum

__device__ __forceinline__ float4 ld4(const float* p){ return *reinterpret_cast<const float4*>(p); }
__device__ __forceinline__ void st4(float* p, float4 v){ *reinterpret_cast<float4*>(p) = v; }

template<bool M>
__device__ __forceinline__ float rop(float a, float b){ return M ? fmaxf(a,b) : fminf(a,b); }

// ---------------------------------------------------------------------------
// Pass 1: Sobel edge (zero-padded), |gx|+|gy|, max over channels, clip(/0.5,0,1)
// ---------------------------------------------------------------------------
#define ET 8

__device__ __forceinline__ void load_row6(const float* p, int x0, float* r)
{
    r[0] = (x0 > 0) ? p[x0-1] : 0.f;
    float4 v = ld4(p + x0); r[1]=v.x; r[2]=v.y; r[3]=v.z; r[4]=v.w;
    r[5] = (x0+4 < WW) ? p[x0+4] : 0.f;
}

__device__ __forceinline__ void zero_row6(float* r)
{
    #pragma unroll
    for (int i=0;i<6;i++) r[i]=0.f;
}

__global__ void __launch_bounds__(256) edge_kernel(const float* __restrict__ t)
{
    int x0  = threadIdx.x << 2;
    int grp = blockIdx.x;
    int b   = grp / (HH/ET);
    int y0  = (grp % (HH/ET)) * ET;

    float g[ET][4];
    #pragma unroll
    for (int k=0;k<ET;k++){ g[k][0]=0.f; g[k][1]=0.f; g[k][2]=0.f; g[k][3]=0.f; }

    #pragma unroll
    for (int c = 0; c < 3; c++) {
        const float* p = t + (size_t)b*3*PLANE + (size_t)c*PLANE;
        float row[3][6];
        if (y0 > 0) load_row6(p + (size_t)(y0-1)*WW, x0, row[0]);
        else        zero_row6(row[0]);
        load_row6(p + (size_t)y0*WW, x0, row[1]);

        #pragma unroll
        for (int k = 0; k < ET; k++) {
            int ynext = y0 + k + 1;
            float* nr = row[(k+2)%3];
            if (ynext <= HH-1) load_row6(p + (size_t)ynext*WW, x0, nr);
            else               zero_row6(nr);

            const float* a  = row[ k   %3];
            const float* bm = row[(k+1)%3];
            const float* cm = row[(k+2)%3];

            float s[6], d[6];
            #pragma unroll
            for (int i=0;i<6;i++){ s[i] = fmaf(2.f, bm[i], a[i]+cm[i]); d[i] = cm[i]-a[i]; }
            #pragma unroll
            for (int j=0;j<4;j++){
                float gx = s[j+2] - s[j];
                float gy = fmaf(2.f, d[j+1], d[j]+d[j+2]);
                g[k][j] = fmaxf(g[k][j], fabsf(gx) + fabsf(gy));
            }
        }
    }

    float* obase = g_E + (size_t)b*PLANE + x0;
    #pragma unroll
    for (int k=0;k<ET;k++){
        float4 o;
        o.x = fminf(g[k][0]*2.f, 1.f);
        o.y = fminf(g[k][1]*2.f, 1.f);
        o.z = fminf(g[k][2]*2.f, 1.f);
        o.w = fminf(g[k][3]*2.f, 1.f);
        st4(obase + (size_t)(y0+k)*WW, o);
    }
}

// ---------------------------------------------------------------------------
// Horizontal 11-tap pool via warp shuffles: 1 ld4 + neighbor-lane halo.
// Window positions a[0..13] = x0-5 .. x0+8 (clamped = replicate at borders).
// ---------------------------------------------------------------------------
template<bool M>
__device__ __forceinline__ float4 hrow11_shfl(const float* __restrict__ p, int x0, int lane)
{
    float4 v = ld4(p + x0);
    float4 vm1, vp1;
    vm1.x = __shfl_up_sync(0xffffffffu, v.x, 1);
    vm1.y = __shfl_up_sync(0xffffffffu, v.y, 1);
    vm1.z = __shfl_up_sync(0xffffffffu, v.z, 1);
    vm1.w = __shfl_up_sync(0xffffffffu, v.w, 1);
    float wm2 = __shfl_up_sync(0xffffffffu, v.w, 2);     // x0-5
    vp1.x = __shfl_down_sync(0xffffffffu, v.x, 1);
    vp1.y = __shfl_down_sync(0xffffffffu, v.y, 1);
    vp1.z = __shfl_down_sync(0xffffffffu, v.z, 1);
    vp1.w = __shfl_down_sync(0xffffffffu, v.w, 1);
    float xp2 = __shfl_down_sync(0xffffffffu, v.x, 2);   // x0+8

    if (lane == 0) {
        if (x0 >= 4) vm1 = ld4(p + x0 - 4);
        else { float e = p[0]; vm1.x=e; vm1.y=e; vm1.z=e; vm1.w=e; }
    }
    if (lane <= 1) wm2 = (x0 >= 5) ? p[x0-5] : p[0];
    if (lane == 31) {
        if (x0 + 8 <= WW) vp1 = ld4(p + x0 + 4);
        else { float e = p[WW-1]; vp1.x=e; vp1.y=e; vp1.z=e; vp1.w=e; }
    }
    if (lane >= 30) xp2 = (x0 + 8 <= WW-1) ? p[x0+8] : p[WW-1];

    // a[0]=wm2 a[1..4]=vm1 a[5..8]=v a[9..12]=vp1 a[13]=xp2
    float C = rop<M>(rop<M>(vm1.z, vm1.w), rop<M>(v.x, v.y));     // a[3..6]
    C = rop<M>(C, rop<M>(rop<M>(v.z, v.w), rop<M>(vp1.x, vp1.y))); // +a[7..10]
    float t12 = rop<M>(vm1.x, vm1.y);    // a[1],a[2]
    float t23 = rop<M>(vp1.z, vp1.w);    // a[11],a[12]
    float4 o;
    o.x = rop<M>(C, rop<M>(wm2,  t12));       // a[0..10]
    o.y = rop<M>(C, rop<M>(t12,  vp1.z));     // a[1..11]
    o.z = rop<M>(rop<M>(C, vm1.y), t23);      // a[2..12]
    o.w = rop<M>(rop<M>(C, xp2),   t23);      // a[3..13]
    return o;
}

template<bool M>
__device__ __forceinline__ void hpool11_body(const float* __restrict__ in, float* __restrict__ out)
{
    int row  = blockIdx.x;
    int x0   = threadIdx.x << 2;
    int lane = threadIdx.x & 31;
    float4 o = hrow11_shfl<M>(in + (size_t)row*WW, x0, lane);
    st4(out + (size_t)row*WW + x0, o);
}

__global__ void __launch_bounds__(256) k_hmax11(){ hpool11_body<true >(g_E,  g_A); }
__global__ void __launch_bounds__(256) k_hmin11(){ hpool11_body<false>(g_B2, g_A); }

// ---------------------------------------------------------------------------
// Vertical 11-tap pool, T output rows per block via 11-deep register ring.
// ---------------------------------------------------------------------------
#define VT 8

template<bool M, int T>
__device__ __forceinline__ void vpool11_body(const float* __restrict__ in, float* __restrict__ out)
{
    int x0  = threadIdx.x << 2;
    int grp = blockIdx.x;
    int b   = grp / (HH/T);
    int y0  = (grp % (HH/T)) * T;
    const float* base  = in  + (size_t)b*PLANE + x0;
    float*       obase = out + (size_t)b*PLANE + x0;

    float4 r[11];
    #pragma unroll
    for (int i = 0; i < 10; i++) {
        int yy = y0 - 5 + i; yy = yy < 0 ? 0 : yy;
        r[i] = ld4(base + (size_t)yy*WW);
    }
    #pragma unroll
    for (int k = 0; k < T; k++) {
        int yy = y0 + k + 5; yy = yy > HH-1 ? HH-1 : yy;
        r[(10+k) % 11] = ld4(base + (size_t)yy*WW);
        float4 o = r[0];
        #pragma unroll
        for (int i=1;i<11;i++){
            o.x = rop<M>(o.x, r[i].x); o.y = rop<M>(o.y, r[i].y);
            o.z = rop<M>(o.z, r[i].z); o.w = rop<M>(o.w, r[i].w);
        }
        st4(obase + (size_t)(y0+k)*WW, o);
    }
}

__global__ void __launch_bounds__(256) k_vmax11(){ vpool11_body<true , VT>(g_A, g_B2); }
__global__ void __launch_bounds__(256) k_vmin11(){ vpool11_body<false, VT>(g_A, g_B2); }

// ---------------------------------------------------------------------------
// Fused final kernel: mask = relu(closed-edge) -> 5x5 max -> masked OKLab loss.
// Writes nothing but three atomics. Skipping mask==0 pixels is exact.
// ---------------------------------------------------------------------------
__device__ __forceinline__ float mval(const float* pc, const float* pe, int xx)
{
    xx = xx < 0 ? 0 : (xx > WW-1 ? WW-1 : xx);
    return fmaxf(pc[xx] - pe[xx], 0.f);
}

__device__ __forceinline__ float4 maskrow_h5(const float* __restrict__ pc,
                                             const float* __restrict__ pe,
                                             int x0, int lane)
{
    float4 c = ld4(pc + x0), e = ld4(pe + x0);
    float4 m;
    m.x = fmaxf(c.x - e.x, 0.f); m.y = fmaxf(c.y - e.y, 0.f);
    m.z = fmaxf(c.z - e.z, 0.f); m.w = fmaxf(c.w - e.w, 0.f);

    float mzm1 = __shfl_up_sync(0xffffffffu, m.z, 1);    // x0-2
    float mwm1 = __shfl_up_sync(0xffffffffu, m.w, 1);    // x0-1
    float mxp1 = __shfl_down_sync(0xffffffffu, m.x, 1);  // x0+4
    float myp1 = __shfl_down_sync(0xffffffffu, m.y, 1);  // x0+5
    if (lane == 0)  { mzm1 = mval(pc, pe, x0-2); mwm1 = mval(pc, pe, x0-1); }
    if (lane == 31) { mxp1 = mval(pc, pe, x0+4); myp1 = mval(pc, pe, x0+5); }

    // window m[0..7] = mzm1, mwm1, m.x, m.y, m.z, m.w, mxp1, myp1
    float C   = fmaxf(m.y, m.z);
    float t12 = fmaxf(mwm1, m.x);
    float t56 = fmaxf(m.w, mxp1);
    float4 o;
    o.x = fmaxf(C, fmaxf(mzm1, t12));
    o.y = fmaxf(C, fmaxf(t12,  m.w));
    o.z = fmaxf(fmaxf(C, m.x), t56);
    o.w = fmaxf(fmaxf(C, myp1), t56);
    return o;
}

__device__ __forceinline__ float s2l(float x)
{
    x = fminf(fmaxf(x, 0.f), 1.f);
    return (x <= 0.04045f) ? x * (1.f/12.92f)
                           : __powf((x + 0.055f) * (1.f/1.055f), 2.4f);
}

__device__ __forceinline__ void oklab_ab(float r, float g, float bl, float& A, float& Bc)
{
    float lr = s2l(r), lg = s2l(g), lb = s2l(bl);
    float l = 0.4122214708f*lr + 0.5363325363f*lg + 0.0514459929f*lb;
    float m = 0.2119034982f*lr + 0.6806995451f*lg + 0.1073969566f*lb;
    float s = 0.0883024619f*lr + 0.2817188376f*lg + 0.6299787005f*lb;
    l = cbrtf(fmaxf(l, 1e-10f));
    m = cbrtf(fmaxf(m, 1e-10f));
    s = cbrtf(fmaxf(s, 1e-10f));
    A  = 1.9779984951f*l - 2.428592205f*m + 0.4505937099f*s;
    Bc = 0.0259040371f*l + 0.7827717662f*m - 0.808675766f*s;
}

#define MT 8

__global__ void __launch_bounds__(256) k_maskloss(const float* __restrict__ pred,
                                                  const float* __restrict__ tgt)
{
    int x0   = threadIdx.x << 2;
    int lane = threadIdx.x & 31;
    int grp  = blockIdx.x;
    int b    = grp / (HH/MT);
    int y0   = (grp % (HH/MT)) * MT;
    const float* cb = g_B2 + (size_t)b*PLANE;   // closed
    const float* eb = g_E  + (size_t)b*PLANE;   // edge

    float msum = 0.f, chroma = 0.f, hue = 0.f;

    float4 r[5];
    #pragma unroll
    for (int i = 0; i < 4; i++) {
        int yy = y0 - 2 + i; yy = yy < 0 ? 0 : yy;
        r[i] = maskrow_h5(cb + (size_t)yy*WW, eb + (size_t)yy*WW, x0, lane);
    }
    #pragma unroll
    for (int k = 0; k < MT; k++) {
        int yy = y0 + k + 2; yy = yy > HH-1 ? HH-1 : yy;
        r[(4+k) % 5] = maskrow_h5(cb + (size_t)yy*WW, eb + (size_t)yy*WW, x0, lane);
        float4 o = r[0];
        #pragma unroll
        for (int i=1;i<5;i++){
            o.x = fmaxf(o.x, r[i].x); o.y = fmaxf(o.y, r[i].y);
            o.z = fmaxf(o.z, r[i].z); o.w = fmaxf(o.w, r[i].w);
        }
        msum += (o.x + o.y) + (o.z + o.w);
        if (o.x > 0.f || o.y > 0.f || o.z > 0.f || o.w > 0.f) {
            size_t base = (size_t)b*3*PLANE + (size_t)(y0+k)*WW + x0;
            float mv[4] = {o.x, o.y, o.z, o.w};
            #pragma unroll 1
            for (int j = 0; j < 4; j++) {
                float m = mv[j];
                if (m > 0.f) {
                    float pa,pb,ta,tb;
                    oklab_ab(pred[base+j], pred[base+j+PLANE], pred[base+j+2*PLANE], pa, pb);
                    oklab_ab(tgt [base+j], tgt [base+j+PLANE], tgt [base+j+2*PLANE], ta, tb);
                    float Cp = sqrtf(fmaf(pa,pa, pb*pb) + 1e-12f);
                    float Cg = sqrtf(fmaf(ta,ta, tb*tb) + 1e-12f);
                    chroma += fabsf(Cp - Cg) * m;
                    float cosd = (pa*ta + pb*tb) / (Cp*Cg + 1e-12f);
                    cosd = fminf(fmaxf(cosd, -1.f), 1.f);
                    hue += fmaxf(Cg, 0.01f) * (1.f - cosd) * m;
                }
            }
        }
    }

    #pragma unroll
    for (int o=16; o; o>>=1){
        msum   += __shfl_xor_sync(0xffffffffu, msum,   o);
        chroma += __shfl_xor_sync(0xffffffffu, chroma, o);
        hue    += __shfl_xor_sync(0xffffffffu, hue,    o);
    }
    __shared__ float sm[3][8];
    int w = threadIdx.x >> 5;
    if (lane == 0){ sm[0][w]=msum; sm[1][w]=chroma; sm[2][w]=hue; }
    __syncthreads();
    if (threadIdx.x == 0){
        float a=0.f, c=0.f, h=0.f;
        #pragma unroll
        for (int i=0;i<8;i++){ a+=sm[0][i]; c+=sm[1][i]; h+=sm[2][i]; }
        atomicAdd(&g_acc[0], a);
        atomicAdd(&g_acc[1], c);
        atomicAdd(&g_acc[2], h);
    }
}

__global__ void k_zero(){ if (threadIdx.x < 3) g_acc[threadIdx.x] = 0.f; }

__global__ void k_fin(float* out)
{
    float ms = fmaxf(g_acc[0], 1.f);
    out[0] = g_acc[1]/ms + 2.f*(g_acc[2]/ms);
}

// ---------------------------------------------------------------------------
extern "C" void kernel_launch(void* const* d_in, const int* in_sizes, int n_in,
                              void* d_out, int out_size)
{
    const float* pred = (const float*)d_in[0];
    const float* tgt  = (const float*)d_in[1];
    float* out = (float*)d_out;

    const int rows  = BBATCH*HH;        // 8192
    const int egrid = BBATCH*HH/ET;     // 1024
    const int vgrid = BBATCH*HH/VT;     // 1024
    const int mgrid = BBATCH*HH/MT;     // 1024
    dim3 blk(256);

    k_zero     <<<1, 32>>>();
    edge_kernel<<<egrid, blk>>>(tgt);     // target -> g_E
    k_hmax11   <<<rows,  blk>>>();        // g_E  -> g_A
    k_vmax11   <<<vgrid, blk>>>();        // g_A  -> g_B2 (dilated)
    k_hmin11   <<<rows,  blk>>>();        // g_B2 -> g_A
    k_vmin11   <<<vgrid, blk>>>();        // g_A  -> g_B2 (closed)
    k_maskloss <<<mgrid, blk>>>(pred, tgt); // (g_B2, g_E, pred, tgt) -> g_acc
    k_fin      <<<1, 1>>>(out);
}

// round 7
// speedup vs baseline: 1.0772x; 1.0289x over previous
#include <cuda_runtime.h>
#include <math.h>

#define HH 1024
#define WW 1024
#define BBATCH 8
#define PLANE (HH*WW)          // 1<<20
#define NPIX (BBATCH*PLANE)    // 8<<20

__device__ float g_E[NPIX];    // edge_soft
__device__ float g_A[NPIX];    // ping
__device__ float g_B2[NPIX];   // pong
__device__ float g_acc[3];     // mask_sum, chroma_sum, hue_sum

__device__ __forceinline__ float4 ld4(const float* p){ return *reinterpret_cast<const float4*>(p); }
__device__ __forceinline__ void st4(float* p, float4 v){ *reinterpret_cast<float4*>(p) = v; }
__device__ __forceinline__ float2 ld2(const float* p){ return *reinterpret_cast<const float2*>(p); }
__device__ __forceinline__ void st2(float* p, float2 v){ *reinterpret_cast<float2*>(p) = v; }

template<bool M>
__device__ __forceinline__ float rop(float a, float b){ return M ? fmaxf(a,b) : fminf(a,b); }

// ---------------------------------------------------------------------------
// Pass 1: Sobel edge (zero-padded), |gx|+|gy|, max over channels, clip(/0.5,0,1)
// ---------------------------------------------------------------------------
#define ET 8

__device__ __forceinline__ void load_row6(const float* p, int x0, float* r)
{
    r[0] = (x0 > 0) ? p[x0-1] : 0.f;
    float4 v = ld4(p + x0); r[1]=v.x; r[2]=v.y; r[3]=v.z; r[4]=v.w;
    r[5] = (x0+4 < WW) ? p[x0+4] : 0.f;
}

__device__ __forceinline__ void zero_row6(float* r)
{
    #pragma unroll
    for (int i=0;i<6;i++) r[i]=0.f;
}

__global__ void __launch_bounds__(256) edge_kernel(const float* __restrict__ t)
{
    int x0  = threadIdx.x << 2;
    int grp = blockIdx.x;
    int b   = grp / (HH/ET);
    int y0  = (grp % (HH/ET)) * ET;

    float g[ET][4];
    #pragma unroll
    for (int k=0;k<ET;k++){ g[k][0]=0.f; g[k][1]=0.f; g[k][2]=0.f; g[k][3]=0.f; }

    #pragma unroll
    for (int c = 0; c < 3; c++) {
        const float* p = t + (size_t)b*3*PLANE + (size_t)c*PLANE;
        float row[3][6];
        if (y0 > 0) load_row6(p + (size_t)(y0-1)*WW, x0, row[0]);
        else        zero_row6(row[0]);
        load_row6(p + (size_t)y0*WW, x0, row[1]);

        #pragma unroll
        for (int k = 0; k < ET; k++) {
            int ynext = y0 + k + 1;
            float* nr = row[(k+2)%3];
            if (ynext <= HH-1) load_row6(p + (size_t)ynext*WW, x0, nr);
            else               zero_row6(nr);

            const float* a  = row[ k   %3];
            const float* bm = row[(k+1)%3];
            const float* cm = row[(k+2)%3];

            float s[6], d[6];
            #pragma unroll
            for (int i=0;i<6;i++){ s[i] = fmaf(2.f, bm[i], a[i]+cm[i]); d[i] = cm[i]-a[i]; }
            #pragma unroll
            for (int j=0;j<4;j++){
                float gx = s[j+2] - s[j];
                float gy = fmaf(2.f, d[j+1], d[j]+d[j+2]);
                g[k][j] = fmaxf(g[k][j], fabsf(gx) + fabsf(gy));
            }
        }
    }

    float* obase = g_E + (size_t)b*PLANE + x0;
    #pragma unroll
    for (int k=0;k<ET;k++){
        float4 o;
        o.x = fminf(g[k][0]*2.f, 1.f);
        o.y = fminf(g[k][1]*2.f, 1.f);
        o.z = fminf(g[k][2]*2.f, 1.f);
        o.w = fminf(g[k][3]*2.f, 1.f);
        st4(obase + (size_t)(y0+k)*WW, o);
    }
}

// ---------------------------------------------------------------------------
// Horizontal 11-tap pool: 5 overlapping ld4 (L1 catches reuse), shared-prefix.
// ---------------------------------------------------------------------------
template<bool M>
__device__ __forceinline__ void hpool11_body(const float* __restrict__ in, float* __restrict__ out)
{
    int row = blockIdx.x;
    const float* p = in + (size_t)row*WW;
    int x0 = threadIdx.x << 2;
    float a[14];   // positions x0-5 .. x0+8
    if (x0 >= 8 && x0 <= WW-12) {
        float4 v0 = ld4(p+x0-8), v1 = ld4(p+x0-4), v2 = ld4(p+x0), v3 = ld4(p+x0+4), v4 = ld4(p+x0+8);
        a[0]=v0.w;
        a[1]=v1.x; a[2]=v1.y; a[3]=v1.z; a[4]=v1.w;
        a[5]=v2.x; a[6]=v2.y; a[7]=v2.z; a[8]=v2.w;
        a[9]=v3.x; a[10]=v3.y; a[11]=v3.z; a[12]=v3.w;
        a[13]=v4.x;
    } else {
        #pragma unroll
        for (int i=0;i<14;i++){
            int xx = x0-5+i; xx = xx < 0 ? 0 : (xx > WW-1 ? WW-1 : xx);
            a[i] = p[xx];
        }
    }
    float C = a[3];
    #pragma unroll
    for (int i=4;i<=10;i++) C = rop<M>(C, a[i]);
    float t12 = rop<M>(a[1],  a[2]);
    float t23 = rop<M>(a[11], a[12]);
    float4 o;
    o.x = rop<M>(C, rop<M>(a[0], t12));
    o.y = rop<M>(C, rop<M>(t12,  a[11]));
    o.z = rop<M>(rop<M>(C, a[2]),  t23);
    o.w = rop<M>(rop<M>(C, a[13]), t23);
    st4(out + (size_t)row*WW + x0, o);
}

__global__ void __launch_bounds__(256) k_hmax11(){ hpool11_body<true >(g_E,  g_A); }
__global__ void __launch_bounds__(256) k_hmin11(){ hpool11_body<false>(g_B2, g_A); }

// ---------------------------------------------------------------------------
// Vertical 11-tap pool, float2 per thread (22-reg ring -> high occupancy),
// T output rows per block via 11-deep register ring. 512 threads/block.
// ---------------------------------------------------------------------------
#define VT 16

template<bool M, int T>
__device__ __forceinline__ void vpool11_body(const float* __restrict__ in, float* __restrict__ out)
{
    int x0  = threadIdx.x << 1;           // 512 threads cover 1024 cols
    int grp = blockIdx.x;
    int b   = grp / (HH/T);
    int y0  = (grp % (HH/T)) * T;
    const float* base  = in  + (size_t)b*PLANE + x0;
    float*       obase = out + (size_t)b*PLANE + x0;

    float2 r[11];
    #pragma unroll
    for (int i = 0; i < 10; i++) {
        int yy = y0 - 5 + i; yy = yy < 0 ? 0 : yy;
        r[i] = ld2(base + (size_t)yy*WW);
    }
    #pragma unroll
    for (int k = 0; k < T; k++) {
        int yy = y0 + k + 5; yy = yy > HH-1 ? HH-1 : yy;
        r[(10+k) % 11] = ld2(base + (size_t)yy*WW);
        float2 o = r[0];
        #pragma unroll
        for (int i=1;i<11;i++){
            o.x = rop<M>(o.x, r[i].x); o.y = rop<M>(o.y, r[i].y);
        }
        st2(obase + (size_t)(y0+k)*WW, o);
    }
}

__global__ void __launch_bounds__(512) k_vmax11(){ vpool11_body<true , VT>(g_A, g_B2); }
__global__ void __launch_bounds__(512) k_vmin11(){ vpool11_body<false, VT>(g_A, g_B2); }

// ---------------------------------------------------------------------------
// Fused final kernel: mask = relu(closed-edge) -> 5x5 max -> masked OKLab loss.
// h5 via direct ld4 windows; v5 via 5-deep register ring. Writes only atomics.
// ---------------------------------------------------------------------------
__device__ __forceinline__ float4 maskrow_h5(const float* __restrict__ pc,
                                             const float* __restrict__ pe, int x0)
{
    float m[8];   // positions x0-2 .. x0+5
    if (x0 >= 4 && x0 <= WW-8) {
        float4 c0 = ld4(pc+x0-4), c1 = ld4(pc+x0), c2 = ld4(pc+x0+4);
        float4 e0 = ld4(pe+x0-4), e1 = ld4(pe+x0), e2 = ld4(pe+x0+4);
        m[0]=fmaxf(c0.z-e0.z,0.f); m[1]=fmaxf(c0.w-e0.w,0.f);
        m[2]=fmaxf(c1.x-e1.x,0.f); m[3]=fmaxf(c1.y-e1.y,0.f);
        m[4]=fmaxf(c1.z-e1.z,0.f); m[5]=fmaxf(c1.w-e1.w,0.f);
        m[6]=fmaxf(c2.x-e2.x,0.f); m[7]=fmaxf(c2.y-e2.y,0.f);
    } else {
        #pragma unroll
        for (int i=0;i<8;i++){
            int xx = x0-2+i; xx = xx < 0 ? 0 : (xx > WW-1 ? WW-1 : xx);
            m[i] = fmaxf(pc[xx]-pe[xx], 0.f);
        }
    }
    float C   = fmaxf(m[3], m[4]);
    float t12 = fmaxf(m[1], m[2]);
    float t56 = fmaxf(m[5], m[6]);
    float4 o;
    o.x = fmaxf(C, fmaxf(m[0], t12));
    o.y = fmaxf(C, fmaxf(t12,  m[5]));
    o.z = fmaxf(fmaxf(C, m[2]), t56);
    o.w = fmaxf(fmaxf(C, m[7]), t56);
    return o;
}

__device__ __forceinline__ float s2l(float x)
{
    x = fminf(fmaxf(x, 0.f), 1.f);
    return (x <= 0.04045f) ? x * (1.f/12.92f)
                           : __powf((x + 0.055f) * (1.f/1.055f), 2.4f);
}

__device__ __forceinline__ void oklab_ab(float r, float g, float bl, float& A, float& Bc)
{
    float lr = s2l(r), lg = s2l(g), lb = s2l(bl);
    float l = 0.4122214708f*lr + 0.5363325363f*lg + 0.0514459929f*lb;
    float m = 0.2119034982f*lr + 0.6806995451f*lg + 0.1073969566f*lb;
    float s = 0.0883024619f*lr + 0.2817188376f*lg + 0.6299787005f*lb;
    l = cbrtf(fmaxf(l, 1e-10f));
    m = cbrtf(fmaxf(m, 1e-10f));
    s = cbrtf(fmaxf(s, 1e-10f));
    A  = 1.9779984951f*l - 2.428592205f*m + 0.4505937099f*s;
    Bc = 0.0259040371f*l + 0.7827717662f*m - 0.808675766f*s;
}

#define MT 8

__global__ void __launch_bounds__(256) k_maskloss(const float* __restrict__ pred,
                                                  const float* __restrict__ tgt)
{
    int x0   = threadIdx.x << 2;
    int grp  = blockIdx.x;
    int b    = grp / (HH/MT);
    int y0   = (grp % (HH/MT)) * MT;
    const float* cb = g_B2 + (size_t)b*PLANE;   // closed
    const float* eb = g_E  + (size_t)b*PLANE;   // edge

    float msum = 0.f, chroma = 0.f, hue = 0.f;

    float4 r[5];
    #pragma unroll
    for (int i = 0; i < 4; i++) {
        int yy = y0 - 2 + i; yy = yy < 0 ? 0 : yy;
        r[i] = maskrow_h5(cb + (size_t)yy*WW, eb + (size_t)yy*WW, x0);
    }
    #pragma unroll
    for (int k = 0; k < MT; k++) {
        int yy = y0 + k + 2; yy = yy > HH-1 ? HH-1 : yy;
        r[(4+k) % 5] = maskrow_h5(cb + (size_t)yy*WW, eb + (size_t)yy*WW, x0);
        float4 o = r[0];
        #pragma unroll
        for (int i=1;i<5;i++){
            o.x = fmaxf(o.x, r[i].x); o.y = fmaxf(o.y, r[i].y);
            o.z = fmaxf(o.z, r[i].z); o.w = fmaxf(o.w, r[i].w);
        }
        msum += (o.x + o.y) + (o.z + o.w);
        if (o.x > 0.f || o.y > 0.f || o.z > 0.f || o.w > 0.f) {
            size_t base = (size_t)b*3*PLANE + (size_t)(y0+k)*WW + x0;
            float mv[4] = {o.x, o.y, o.z, o.w};
            #pragma unroll 1
            for (int j = 0; j < 4; j++) {
                float m = mv[j];
                if (m > 0.f) {
                    float pa,pb,ta,tb;
                    oklab_ab(pred[base+j], pred[base+j+PLANE], pred[base+j+2*PLANE], pa, pb);
                    oklab_ab(tgt [base+j], tgt [base+j+PLANE], tgt [base+j+2*PLANE], ta, tb);
                    float Cp = sqrtf(fmaf(pa,pa, pb*pb) + 1e-12f);
                    float Cg = sqrtf(fmaf(ta,ta, tb*tb) + 1e-12f);
                    chroma += fabsf(Cp - Cg) * m;
                    float cosd = (pa*ta + pb*tb) / (Cp*Cg + 1e-12f);
                    cosd = fminf(fmaxf(cosd, -1.f), 1.f);
                    hue += fmaxf(Cg, 0.01f) * (1.f - cosd) * m;
                }
            }
        }
    }

    #pragma unroll
    for (int o=16; o; o>>=1){
        msum   += __shfl_xor_sync(0xffffffffu, msum,   o);
        chroma += __shfl_xor_sync(0xffffffffu, chroma, o);
        hue    += __shfl_xor_sync(0xffffffffu, hue,    o);
    }
    __shared__ float sm[3][8];
    int w = threadIdx.x >> 5, lane = threadIdx.x & 31;
    if (lane == 0){ sm[0][w]=msum; sm[1][w]=chroma; sm[2][w]=hue; }
    __syncthreads();
    if (threadIdx.x == 0){
        float a=0.f, c=0.f, h=0.f;
        #pragma unroll
        for (int i=0;i<8;i++){ a+=sm[0][i]; c+=sm[1][i]; h+=sm[2][i]; }
        atomicAdd(&g_acc[0], a);
        atomicAdd(&g_acc[1], c);
        atomicAdd(&g_acc[2], h);
    }
}

__global__ void k_zero(){ if (threadIdx.x < 3) g_acc[threadIdx.x] = 0.f; }

__global__ void k_fin(float* out)
{
    float ms = fmaxf(g_acc[0], 1.f);
    out[0] = g_acc[1]/ms + 2.f*(g_acc[2]/ms);
}

// ---------------------------------------------------------------------------
extern "C" void kernel_launch(void* const* d_in, const int* in_sizes, int n_in,
                              void* d_out, int out_size)
{
    const float* pred = (const float*)d_in[0];
    const float* tgt  = (const float*)d_in[1];
    float* out = (float*)d_out;

    const int rows  = BBATCH*HH;        // 8192
    const int egrid = BBATCH*HH/ET;     // 1024
    const int vgrid = BBATCH*HH/VT;     // 512 (512-thread blocks)
    const int mgrid = BBATCH*HH/MT;     // 1024
    dim3 blk(256);

    k_zero     <<<1, 32>>>();
    edge_kernel<<<egrid, blk>>>(tgt);       // target -> g_E
    k_hmax11   <<<rows,  blk>>>();          // g_E  -> g_A
    k_vmax11   <<<vgrid, 512>>>();          // g_A  -> g_B2 (dilated)
    k_hmin11   <<<rows,  blk>>>();          // g_B2 -> g_A
    k_vmin11   <<<vgrid, 512>>>();          // g_A  -> g_B2 (closed)
    k_maskloss <<<mgrid, blk>>>(pred, tgt); // (g_B2, g_E, pred, tgt) -> g_acc
    k_fin      <<<1, 1>>>(out);
}